// round 5
// baseline (speedup 1.0000x reference)
#include <cuda_runtime.h>
#include <cstdint>

#define C_DIM  256
#define L_DIM  4096
#define LM_DIM 36864
#define B_DIM  4

__device__ float g_M[C_DIM * C_DIM];   // M[c1][c2] = sum_c W1[c1][c]*W2[c2][256+c]

// ---------------- helpers ----------------
__device__ __forceinline__ uint32_t smem_u32(const void* p) {
    uint32_t a;
    asm("{ .reg .u64 t; cvta.to.shared.u64 t, %1; cvt.u32.u64 %0, t; }" : "=r"(a) : "l"(p));
    return a;
}
__device__ __forceinline__ void cp16(uint32_t dst, const void* src) {
    asm volatile("cp.async.cg.shared.global [%0], [%1], 16;" :: "r"(dst), "l"(src) : "memory");
}
__device__ __forceinline__ void cp_commit() {
    asm volatile("cp.async.commit_group;" ::: "memory");
}
template <int N>
__device__ __forceinline__ void cp_wait() {
    asm volatile("cp.async.wait_group %0;" :: "n"(N) : "memory");
}
__device__ __forceinline__ uint32_t tf32_hi(float v) {
    uint32_t h;
    asm("cvt.rna.tf32.f32 %0, %1;" : "=r"(h) : "f"(v));
    return h;
}
__device__ __forceinline__ uint32_t tf32_lo(float v, uint32_t hi) {
    float l = v - __uint_as_float(hi);
    uint32_t r;
    asm("cvt.rna.tf32.f32 %0, %1;" : "=r"(r) : "f"(l));
    return r;
}
__device__ __forceinline__ void mma8(float* d, const uint32_t* a, const uint32_t* b) {
    asm volatile(
        "mma.sync.aligned.m16n8k8.row.col.f32.tf32.tf32.f32 "
        "{%0,%1,%2,%3}, {%4,%5,%6,%7}, {%8,%9}, {%0,%1,%2,%3};"
        : "+f"(d[0]), "+f"(d[1]), "+f"(d[2]), "+f"(d[3])
        : "r"(a[0]), "r"(a[1]), "r"(a[2]), "r"(a[3]), "r"(b[0]), "r"(b[1]));
}

// ---------------- Kernel 1: M[c1][c2], 8-way k-split + atomicAdd ----------------
__global__ __launch_bounds__(256) void k1_M(const float* __restrict__ W1,
                                            const float* __restrict__ W2) {
    __shared__ float A[32][33];
    __shared__ float Bs[32][33];
    const int t = threadIdx.x;
    const int c2_0 = blockIdx.x * 32, c1_0 = blockIdx.y * 32, kk = blockIdx.z * 32;
    {
        int r = t >> 3, c4 = (t & 7) * 4;
        float4 a = *(const float4*)&W1[(c1_0 + r) * 768 + kk + c4];
        A[r][c4] = a.x; A[r][c4 + 1] = a.y; A[r][c4 + 2] = a.z; A[r][c4 + 3] = a.w;
        float4 b = *(const float4*)&W2[(c2_0 + r) * 768 + 256 + kk + c4];
        Bs[r][c4] = b.x; Bs[r][c4 + 1] = b.y; Bs[r][c4 + 2] = b.z; Bs[r][c4 + 3] = b.w;
    }
    __syncthreads();
    const int ty = t >> 4, tx = t & 15;
    float a00 = 0.f, a01 = 0.f, a10 = 0.f, a11 = 0.f;
    #pragma unroll
    for (int k = 0; k < 32; ++k) {
        float x0 = A[ty * 2][k], x1 = A[ty * 2 + 1][k];
        float y0 = Bs[tx * 2][k], y1 = Bs[tx * 2 + 1][k];
        a00 += x0 * y0; a01 += x0 * y1; a10 += x1 * y0; a11 += x1 * y1;
    }
    atomicAdd(&g_M[(c1_0 + ty * 2)     * 256 + c2_0 + tx * 2],     a00);
    atomicAdd(&g_M[(c1_0 + ty * 2)     * 256 + c2_0 + tx * 2 + 1], a01);
    atomicAdd(&g_M[(c1_0 + ty * 2 + 1) * 256 + c2_0 + tx * 2],     a10);
    atomicAdd(&g_M[(c1_0 + ty * 2 + 1) * 256 + c2_0 + tx * 2 + 1], a11);
}

// ---------------- Fused kernel: GEMM(32l x 256c2) in smem -> scores -> argmax ----------------
// A chunk: [k=32][m=32] pitch 40; B chunk: [k=32][n=256] pitch 264. Double buffered.
// U kept in smem [c2=256][l=32] pitch 36 (reuses chunk buffers). 2 CTAs/SM.
#define PA2   40
#define PB2   264
#define CHA_F (32 * PA2)                    // 1280 floats
#define CHB_F (32 * PB2)                    // 8448 floats
#define OFF_A0 0
#define OFF_A1 CHA_F
#define OFF_B0 (2 * CHA_F)
#define OFF_B1 (2 * CHA_F + CHB_F)
#define KF_SMEM ((2 * CHA_F + 2 * CHB_F) * 4)   // 77824 B
#define UPIT 36

__global__ __launch_bounds__(256, 2) void kF(const float* __restrict__ HSI,
                                             const float* __restrict__ MSI,
                                             float* __restrict__ out) {
    extern __shared__ float sm[];
    __shared__ float sc[288];
    const int t = threadIdx.x, wid = t >> 5, lane = t & 31;
    const int g = lane >> 2, t4 = lane & 3;
    const int b = blockIdx.y, l0 = blockIdx.x * 32;
    const float* Hb = HSI + (size_t)b * C_DIM * L_DIM;
    const uint32_t sbase = smem_u32(sm);

    // warp grid: 2(m) x 4(n); each warp: 16 l x 64 c2
    const int mw = (wid >> 2) * 16;        // 0 or 16
    const int nq = (wid & 3) * 64;         // 0,64,128,192

    float d[8][4];
    #pragma unroll
    for (int nt = 0; nt < 8; ++nt)
        #pragma unroll
        for (int i = 0; i < 4; ++i) d[nt][i] = 0.f;

    // copy thread mappings
    const int ar = t >> 3, ac = (t & 7) * 4;      // A: 32 rows x 8 quads

    // chunk 0
    {
        cp16(sbase + (uint32_t)((OFF_A0 + ar * PA2 + ac) * 4),
             &Hb[(size_t)ar * L_DIM + l0 + ac]);
        #pragma unroll
        for (int q = 0; q < 8; ++q) {
            int idx = t + q * 256;
            int r = idx >> 6, qc = (idx & 63) * 4;
            cp16(sbase + (uint32_t)((OFF_B0 + r * PB2 + qc) * 4), &g_M[r * 256 + qc]);
        }
        cp_commit();
    }

    for (int ch = 0; ch < 8; ++ch) {
        if (ch < 7) {
            const int p = (ch + 1) & 1;
            const int kk = (ch + 1) * 32;
            const int offA = p ? OFF_A1 : OFF_A0;
            const int offB = p ? OFF_B1 : OFF_B0;
            cp16(sbase + (uint32_t)((offA + ar * PA2 + ac) * 4),
                 &Hb[(size_t)(kk + ar) * L_DIM + l0 + ac]);
            #pragma unroll
            for (int q = 0; q < 8; ++q) {
                int idx = t + q * 256;
                int r = idx >> 6, qc = (idx & 63) * 4;
                cp16(sbase + (uint32_t)((offB + r * PB2 + qc) * 4),
                     &g_M[(kk + r) * 256 + qc]);
            }
            cp_commit();
            cp_wait<1>();
        } else {
            cp_wait<0>();
        }
        __syncthreads();

        const float* As = sm + ((ch & 1) ? OFF_A1 : OFF_A0);
        const float* Bs = sm + ((ch & 1) ? OFF_B1 : OFF_B0);

        #pragma unroll
        for (int s = 0; s < 4; ++s) {
            const int r0 = 8 * s + t4, r1 = r0 + 4;
            uint32_t ah[4], al[4];
            {
                const int m0 = mw + g;
                float v0 = As[r0 * PA2 + m0];
                float v1 = As[r0 * PA2 + m0 + 8];
                float v2 = As[r1 * PA2 + m0];
                float v3 = As[r1 * PA2 + m0 + 8];
                ah[0] = tf32_hi(v0); al[0] = tf32_lo(v0, ah[0]);
                ah[1] = tf32_hi(v1); al[1] = tf32_lo(v1, ah[1]);
                ah[2] = tf32_hi(v2); al[2] = tf32_lo(v2, ah[2]);
                ah[3] = tf32_hi(v3); al[3] = tf32_lo(v3, ah[3]);
            }
            #pragma unroll
            for (int ng = 0; ng < 2; ++ng) {
                uint32_t bh[4][2], bl[4][2];
                #pragma unroll
                for (int q = 0; q < 4; ++q) {
                    int n0 = nq + 8 * (ng * 4 + q) + g;
                    float v0 = Bs[r0 * PB2 + n0];
                    float v1 = Bs[r1 * PB2 + n0];
                    bh[q][0] = tf32_hi(v0); bl[q][0] = tf32_lo(v0, bh[q][0]);
                    bh[q][1] = tf32_hi(v1); bl[q][1] = tf32_lo(v1, bh[q][1]);
                }
                #pragma unroll
                for (int q = 0; q < 4; ++q) mma8(d[ng * 4 + q], ah, bh[q]);
                #pragma unroll
                for (int q = 0; q < 4; ++q) mma8(d[ng * 4 + q], ah, bl[q]);
                #pragma unroll
                for (int q = 0; q < 4; ++q) mma8(d[ng * 4 + q], al, bh[q]);
            }
        }
        __syncthreads();
    }

    // ---- stage U into smem (reuse chunk buffers): us[c2][l_local], pitch 36 ----
    float* Usm = sm;
    #pragma unroll
    for (int nt = 0; nt < 8; ++nt) {
        int col0 = nq + 8 * nt + 2 * t4;
        int row0 = mw + g;
        Usm[col0 * UPIT + row0]           = d[nt][0];
        Usm[(col0 + 1) * UPIT + row0]     = d[nt][1];
        Usm[col0 * UPIT + row0 + 8]       = d[nt][2];
        Usm[(col0 + 1) * UPIT + row0 + 8] = d[nt][3];
    }
    __syncthreads();

    // ---- score phase: 288 m-values, streamed MSI, coalesced ----
    const float* mp = MSI + (size_t)b * C_DIM * LM_DIM + (size_t)l0 * 9;
    for (int i = t; i < 288; i += 256) {
        const int ll = i / 9;
        const float* col = mp + i;
        float acc = 0.f;
        #pragma unroll 8
        for (int c2 = 0; c2 < 256; ++c2)
            acc += Usm[c2 * UPIT + ll] * col[(size_t)c2 * LM_DIM];
        sc[i] = acc;
    }
    __syncthreads();

    // ---- argmax -> offsets ----
    if (t < 32) {
        float best = sc[t * 9];
        int bn = 0;
        #pragma unroll
        for (int j = 1; j < 9; ++j) {
            float v = sc[t * 9 + j];
            if (v > best) { best = v; bn = j; }   // strict > = first max (jnp.argmax)
        }
        float2 o = make_float2((float)(bn / 3) - 1.f, (float)(bn % 3) - 1.f);
        *(float2*)&out[(size_t)(b * L_DIM + l0 + t) * 2] = o;
    }
}

// ---------------- launch ----------------
extern "C" void kernel_launch(void* const* d_in, const int* in_sizes, int n_in,
                              void* d_out, int out_size) {
    const float* HSI = (const float*)d_in[2];
    const float* MSI = (const float*)d_in[3];
    const float* W1  = (const float*)d_in[4];
    const float* W2  = (const float*)d_in[5];
    float* out = (float*)d_out;

    void* mp = nullptr;
    cudaGetSymbolAddress(&mp, g_M);
    cudaMemsetAsync(mp, 0, C_DIM * C_DIM * sizeof(float), 0);

    k1_M<<<dim3(8, 8, 8), 256>>>(W1, W2);

    cudaFuncSetAttribute(kF, cudaFuncAttributeMaxDynamicSharedMemorySize, KF_SMEM);
    kF<<<dim3(128, 4), 256, KF_SMEM>>>(HSI, MSI, out);
}